// round 15
// baseline (speedup 1.0000x reference)
#include <cuda_runtime.h>
#include <cuda_fp16.h>
#include <cstdint>

#define BATCH 8
#define NSEQ  2048
#define DDIM  384

// Scratch (device globals, no allocation): fp16 P copy, fp16 W^T, fp16 PW.
__device__ __half g_Phalf[BATCH * NSEQ * DDIM];
__device__ __half g_WT   [DDIM * DDIM];
__device__ __half g_PW   [BATCH * NSEQ * DDIM];

__device__ __forceinline__ uint32_t smem_u32(const void* p) {
    uint32_t a;
    asm("{ .reg .u64 t; cvta.to.shared.u64 t, %1; cvt.u32.u64 %0, t; }" : "=r"(a) : "l"(p));
    return a;
}
__device__ __forceinline__ void cp_async16(uint32_t dst, const void* src) {
    asm volatile("cp.async.cg.shared.global [%0], [%1], 16;" :: "r"(dst), "l"(src) : "memory");
}
#define CP_COMMIT() asm volatile("cp.async.commit_group;" ::: "memory")
#define CP_WAIT2()  asm volatile("cp.async.wait_group 2;" ::: "memory")

__device__ __forceinline__ void mma_f16(float& d0, float& d1, float& d2, float& d3,
                                        unsigned a0, unsigned a1, unsigned a2, unsigned a3,
                                        unsigned b0, unsigned b1) {
    asm volatile(
        "mma.sync.aligned.m16n8k16.row.col.f32.f16.f16.f32 "
        "{%0,%1,%2,%3}, {%4,%5,%6,%7}, {%8,%9}, {%0,%1,%2,%3};"
        : "+f"(d0), "+f"(d1), "+f"(d2), "+f"(d3)
        : "r"(a0), "r"(a1), "r"(a2), "r"(a3), "r"(b0), "r"(b1));
}

__device__ __forceinline__ void ldsm4(unsigned r[4], uint32_t addr) {
    asm volatile("ldmatrix.sync.aligned.m8n8.x4.shared.b16 {%0,%1,%2,%3}, [%4];"
        : "=r"(r[0]), "=r"(r[1]), "=r"(r[2]), "=r"(r[3]) : "r"(addr));
}

// ============================================================================
// Kernel 0: W (fp32 [k][n]) -> g_WT (fp16 [n][k]).  Tiled smem transpose:
// coalesced reads AND writes.  Grid (12,12), block (32,8).
// ============================================================================
__global__ void wtrans_fast(const float* __restrict__ W) {
    __shared__ float tile[32][33];
    const int kb = blockIdx.x * 32;
    const int nb = blockIdx.y * 32;
    const int tx = threadIdx.x;
    const int ty = threadIdx.y;
    #pragma unroll
    for (int i = 0; i < 4; ++i)
        tile[ty + 8 * i][tx] = W[(size_t)(kb + ty + 8 * i) * DDIM + nb + tx];
    __syncthreads();
    #pragma unroll
    for (int i = 0; i < 4; ++i)
        g_WT[(size_t)(nb + ty + 8 * i) * DDIM + kb + tx] =
            __float2half_rn(tile[tx][ty + 8 * i]);
}

#define NTHR 256
#define BN2  128
#define BK2  64
#define NCHUNK (DDIM / BK2)            // 6
#define ROWB 144
#define B_STG (BN2 * ROWB)             // 18432 B

// ============================================================================
// Kernel 1: PW = P @ W, BM=128 tiles, grid (3,64) per half (rowOff param).
// Phase A: fp32 P rows -> fp16 persistent smem A chunks (+ g_Phalf if jBase==0).
// First two B stages issued BEFORE phase A to overlap latency.
// ============================================================================
#define K1_A_BYTES (NCHUNK * 128 * ROWB)          // 110592
#define SMEM_K1    (K1_A_BYTES + 3 * B_STG)       // 165888

__global__ __launch_bounds__(NTHR, 1)
void gemm_pw_f16(const float* __restrict__ P, int rowOff) {
    extern __shared__ char sm[];
    const uint32_t sm_base = smem_u32(sm);
    const int t    = threadIdx.x;
    const int lane = t & 31;
    const int warp = t >> 5;
    const int wR   = warp & 3;
    const int wC   = warp >> 2;
    const int iBase = rowOff + blockIdx.y * 128;
    const int jBase = blockIdx.x * BN2;

    auto fillB = [&](int c, int s) {
        const uint32_t b_u32 = sm_base + K1_A_BYTES + (uint32_t)(s * B_STG);
        #pragma unroll
        for (int p = 0; p < 4; ++p) {
            int id  = t + p * NTHR;
            int r   = id >> 3;
            int seg = id & 7;
            cp_async16(b_u32 + (uint32_t)(r * ROWB + seg * 16),
                       &g_WT[(size_t)(jBase + r) * DDIM + c * BK2 + seg * 8]);
        }
    };
    // Issue first two B stages up front; they land while phase A converts.
    fillB(0, 0); CP_COMMIT();
    fillB(1, 1); CP_COMMIT();

    // ---- Phase A: fp32 P rows -> fp16 persistent smem (+ g_Phalf if jBase==0)
    #pragma unroll
    for (int ch = 0; ch < NCHUNK; ++ch) {
        const uint32_t aoffb = (uint32_t)(ch * 128 * ROWB);
        #pragma unroll
        for (int p = 0; p < 8; ++p) {               // 128 rows x 16 f4 = 2048
            int id = t + p * NTHR;
            int r  = id >> 4;
            int f4 = id & 15;
            float4 v = *reinterpret_cast<const float4*>(
                &P[(size_t)(iBase + r) * DDIM + ch * 64 + f4 * 4]);
            __half2 h0 = __floats2half2_rn(v.x, v.y);
            __half2 h1 = __floats2half2_rn(v.z, v.w);
            uint2 o;
            o.x = *reinterpret_cast<unsigned*>(&h0);
            o.y = *reinterpret_cast<unsigned*>(&h1);
            *reinterpret_cast<uint2*>(sm + aoffb + r * ROWB + f4 * 8) = o;
            if (jBase == 0)
                *reinterpret_cast<uint2*>(
                    &g_Phalf[(size_t)(iBase + r) * DDIM + ch * 64 + f4 * 4]) = o;
        }
    }
    __syncthreads();

    const int g  = lane >> 3;
    const int rr = lane & 7;
    const uint32_t aoff = (uint32_t)(rr * ROWB + (g & 1) * (8 * ROWB) + (g >> 1) * 16);
    const uint32_t boff = (uint32_t)(rr * ROWB + (g >> 1) * (8 * ROWB) + (g & 1) * 16);

    float acc[2][8][4];
    #pragma unroll
    for (int mt = 0; mt < 2; ++mt)
        #pragma unroll
        for (int nt = 0; nt < 8; ++nt)
            #pragma unroll
            for (int r = 0; r < 4; ++r) acc[mt][nt][r] = 0.f;

    for (int c = 0; c < NCHUNK; ++c) {
        if (c + 2 < NCHUNK) fillB(c + 2, (c + 2) % 3);
        CP_COMMIT();
        CP_WAIT2();
        __syncthreads();

        const uint32_t As = sm_base + (uint32_t)(c * 128 * ROWB);
        const uint32_t Bs = sm_base + K1_A_BYTES + (uint32_t)((c % 3) * B_STG);
        const uint32_t Abase = As + (uint32_t)(wR * 32 * ROWB) + aoff;
        const uint32_t Bbase = Bs + (uint32_t)(wC * 64 * ROWB) + boff;

        #pragma unroll
        for (int ks = 0; ks < 4; ++ks) {
            const uint32_t cb = ks * 32;
            unsigned a[2][4], bf[8][2];
            #pragma unroll
            for (int mt = 0; mt < 2; ++mt)
                ldsm4(a[mt], Abase + (uint32_t)(mt * 16 * ROWB) + cb);
            #pragma unroll
            for (int np = 0; np < 4; ++np) {
                unsigned bq[4];
                ldsm4(bq, Bbase + (uint32_t)(np * 16 * ROWB) + cb);
                bf[2 * np][0]     = bq[0];
                bf[2 * np][1]     = bq[1];
                bf[2 * np + 1][0] = bq[2];
                bf[2 * np + 1][1] = bq[3];
            }
            #pragma unroll
            for (int mt = 0; mt < 2; ++mt)
                #pragma unroll
                for (int nt = 0; nt < 8; ++nt)
                    mma_f16(acc[mt][nt][0], acc[mt][nt][1], acc[mt][nt][2], acc[mt][nt][3],
                            a[mt][0], a[mt][1], a[mt][2], a[mt][3],
                            bf[nt][0], bf[nt][1]);
        }
        __syncthreads();
    }

    #pragma unroll
    for (int mt = 0; mt < 2; ++mt) {
        int r0 = iBase + wR * 32 + mt * 16 + (lane >> 2);
        #pragma unroll
        for (int nt = 0; nt < 8; ++nt) {
            int cc = jBase + wC * 64 + nt * 8 + ((lane & 3) << 1);
            __half2 h01 = __floats2half2_rn(acc[mt][nt][0], acc[mt][nt][1]);
            __half2 h23 = __floats2half2_rn(acc[mt][nt][2], acc[mt][nt][3]);
            *reinterpret_cast<__half2*>(&g_PW[(size_t)r0 * DDIM + cc])       = h01;
            *reinterpret_cast<__half2*>(&g_PW[(size_t)(r0 + 8) * DDIM + cc]) = h23;
        }
    }
}

// ============================================================================
// Kernel 2 (mainloop unchanged — 98.5% of legacy tensor roofline):
// logits[b] = PW[b] @ P[b]^T + bias, BM=256, grid (16,8,4) per half.
// ============================================================================
#define K2_A_STG (256 * ROWB)
#define K2_STG   (K2_A_STG + B_STG)
#define SMEM_K2  (3 * K2_STG)                    // 165888

__global__ __launch_bounds__(NTHR, 1)
void gemm_logits_k2(int batchOff, const float* __restrict__ bias_ptr,
                    float* __restrict__ C) {
    extern __shared__ char sm[];
    const uint32_t sm_base = smem_u32(sm);
    const int t    = threadIdx.x;
    const int lane = t & 31;
    const int warp = t >> 5;
    const int wR   = warp & 3;
    const int wC   = warp >> 2;
    const int batch = batchOff + blockIdx.z;
    const int iBase = blockIdx.y * 256;
    const int jBase = blockIdx.x * BN2;

    const __half* Ag = g_PW    + (size_t)batch * NSEQ * DDIM;
    const __half* Bg = g_Phalf + (size_t)batch * NSEQ * DDIM;
    float* Cb = C + (size_t)batch * NSEQ * NSEQ;

    float acc[4][8][4];
    #pragma unroll
    for (int mt = 0; mt < 4; ++mt)
        #pragma unroll
        for (int nt = 0; nt < 8; ++nt)
            #pragma unroll
            for (int r = 0; r < 4; ++r) acc[mt][nt][r] = 0.f;

    auto fill = [&](int c, int s) {
        const int kc = c * BK2;
        const uint32_t a_u32 = sm_base + (uint32_t)(s * K2_STG);
        const uint32_t b_u32 = a_u32 + K2_A_STG;
        #pragma unroll
        for (int p = 0; p < 8; ++p) {
            int id  = t + p * NTHR;
            int r   = id >> 3;
            int seg = id & 7;
            cp_async16(a_u32 + (uint32_t)(r * ROWB + seg * 16),
                       &Ag[(size_t)(iBase + r) * DDIM + kc + seg * 8]);
        }
        #pragma unroll
        for (int p = 0; p < 4; ++p) {
            int id  = t + p * NTHR;
            int r   = id >> 3;
            int seg = id & 7;
            cp_async16(b_u32 + (uint32_t)(r * ROWB + seg * 16),
                       &Bg[(size_t)(jBase + r) * DDIM + kc + seg * 8]);
        }
    };

    fill(0, 0); CP_COMMIT();
    fill(1, 1); CP_COMMIT();

    const int g  = lane >> 3;
    const int rr = lane & 7;
    const uint32_t aoff = (uint32_t)(rr * ROWB + (g & 1) * (8 * ROWB) + (g >> 1) * 16);
    const uint32_t boff = (uint32_t)(rr * ROWB + (g >> 1) * (8 * ROWB) + (g & 1) * 16);

    for (int c = 0; c < NCHUNK; ++c) {
        if (c + 2 < NCHUNK) fill(c + 2, (c + 2) % 3);
        CP_COMMIT();
        CP_WAIT2();
        __syncthreads();

        const uint32_t As = sm_base + (uint32_t)((c % 3) * K2_STG);
        const uint32_t Bs = As + K2_A_STG;
        const uint32_t Abase = As + (uint32_t)(wR * 64 * ROWB) + aoff;
        const uint32_t Bbase = Bs + (uint32_t)(wC * 64 * ROWB) + boff;

        #pragma unroll
        for (int ks = 0; ks < 4; ++ks) {
            const uint32_t cb = ks * 32;
            unsigned a[4][4], bf[8][2];
            #pragma unroll
            for (int mt = 0; mt < 4; ++mt)
                ldsm4(a[mt], Abase + (uint32_t)(mt * 16 * ROWB) + cb);
            #pragma unroll
            for (int np = 0; np < 4; ++np) {
                unsigned bq[4];
                ldsm4(bq, Bbase + (uint32_t)(np * 16 * ROWB) + cb);
                bf[2 * np][0]     = bq[0];
                bf[2 * np][1]     = bq[1];
                bf[2 * np + 1][0] = bq[2];
                bf[2 * np + 1][1] = bq[3];
            }
            #pragma unroll
            for (int mt = 0; mt < 4; ++mt)
                #pragma unroll
                for (int nt = 0; nt < 8; ++nt)
                    mma_f16(acc[mt][nt][0], acc[mt][nt][1], acc[mt][nt][2], acc[mt][nt][3],
                            a[mt][0], a[mt][1], a[mt][2], a[mt][3],
                            bf[nt][0], bf[nt][1]);
        }
        __syncthreads();
    }

    const float bv = __ldg(bias_ptr);
    #pragma unroll
    for (int mt = 0; mt < 4; ++mt) {
        int r0 = iBase + wR * 64 + mt * 16 + (lane >> 2);
        #pragma unroll
        for (int nt = 0; nt < 8; ++nt) {
            int cc = jBase + wC * 64 + nt * 8 + ((lane & 3) << 1);
            float2 v01 = make_float2(acc[mt][nt][0] + bv, acc[mt][nt][1] + bv);
            float2 v23 = make_float2(acc[mt][nt][2] + bv, acc[mt][nt][3] + bv);
            *reinterpret_cast<float2*>(&Cb[(size_t)r0 * NSEQ + cc])       = v01;
            *reinterpret_cast<float2*>(&Cb[(size_t)(r0 + 8) * NSEQ + cc]) = v23;
        }
    }
}

// ============================================================================
// Launch: 2-way split with overlap.
//   sProd: wtrans; k1(rows 0..8191) -> evA; k1(rows 8192..) -> evB
//   main:  wait evA -> k2(batches 0..3); wait evB -> k2(batches 4..7)
// k1-half2 (192 CTAs) overlaps k2-half1 (512 CTAs), absorbing wave tails.
// ============================================================================
extern "C" void kernel_launch(void* const* d_in, const int* in_sizes, int n_in,
                              void* d_out, int out_size) {
    const float* P  = (const float*)d_in[0];   // [8, 2048, 384]
    const float* W  = (const float*)d_in[1];   // [384, 384]
    const float* bp = (const float*)d_in[2];   // [1]
    float* out = (float*)d_out;                // [8, 2048, 2048]
    (void)in_sizes; (void)n_in; (void)out_size;

    static cudaStream_t sProd = nullptr;
    static cudaEvent_t  e0, evA, evB;
    static bool init_done = false;
    if (!init_done) {
        cudaStreamCreateWithFlags(&sProd, cudaStreamNonBlocking);
        cudaEventCreateWithFlags(&e0,  cudaEventDisableTiming);
        cudaEventCreateWithFlags(&evA, cudaEventDisableTiming);
        cudaEventCreateWithFlags(&evB, cudaEventDisableTiming);
        cudaFuncSetAttribute(gemm_pw_f16,
                             cudaFuncAttributeMaxDynamicSharedMemorySize, SMEM_K1);
        cudaFuncSetAttribute(gemm_logits_k2,
                             cudaFuncAttributeMaxDynamicSharedMemorySize, SMEM_K2);
        init_done = true;
    }

    // Fork producer stream off the (captured) default stream.
    cudaEventRecord(e0, 0);
    cudaStreamWaitEvent(sProd, e0, 0);

    // Producer chain: transpose, then both k1 halves.
    dim3 gwt(DDIM / 32, DDIM / 32, 1);               // (12,12)
    wtrans_fast<<<gwt, dim3(32, 8, 1), 0, sProd>>>(W);

    dim3 g1(DDIM / BN2, (BATCH * NSEQ) / 128 / 2, 1);    // (3, 64) = 192 CTAs
    gemm_pw_f16<<<g1, NTHR, SMEM_K1, sProd>>>(P, 0);
    cudaEventRecord(evA, sProd);
    gemm_pw_f16<<<g1, NTHR, SMEM_K1, sProd>>>(P, (BATCH * NSEQ) / 2);
    cudaEventRecord(evB, sProd);

    // Consumers on the capture stream: each half gated on its producer half.
    dim3 g2(NSEQ / BN2, NSEQ / 256, BATCH / 2);          // (16, 8, 4) = 512 CTAs
    cudaStreamWaitEvent(0, evA, 0);
    gemm_logits_k2<<<g2, NTHR, SMEM_K2>>>(0, bp, out);
    cudaStreamWaitEvent(0, evB, 0);
    gemm_logits_k2<<<g2, NTHR, SMEM_K2>>>(BATCH / 2, bp, out);
}

// round 16
// speedup vs baseline: 1.0984x; 1.0984x over previous
#include <cuda_runtime.h>
#include <cuda_fp16.h>
#include <cstdint>

#define BATCH 8
#define NSEQ  2048
#define DDIM  384

// Scratch (device globals, no allocation): fp16 P copy, fp16 W^T, fp16 PW.
__device__ __half g_Phalf[BATCH * NSEQ * DDIM];
__device__ __half g_WT   [DDIM * DDIM];
__device__ __half g_PW   [BATCH * NSEQ * DDIM];

__device__ __forceinline__ uint32_t smem_u32(const void* p) {
    uint32_t a;
    asm("{ .reg .u64 t; cvta.to.shared.u64 t, %1; cvt.u32.u64 %0, t; }" : "=r"(a) : "l"(p));
    return a;
}
__device__ __forceinline__ void cp_async16(uint32_t dst, const void* src) {
    asm volatile("cp.async.cg.shared.global [%0], [%1], 16;" :: "r"(dst), "l"(src) : "memory");
}
#define CP_COMMIT() asm volatile("cp.async.commit_group;" ::: "memory")
#define CP_WAIT2()  asm volatile("cp.async.wait_group 2;" ::: "memory")

__device__ __forceinline__ void mma_f16(float& d0, float& d1, float& d2, float& d3,
                                        unsigned a0, unsigned a1, unsigned a2, unsigned a3,
                                        unsigned b0, unsigned b1) {
    asm volatile(
        "mma.sync.aligned.m16n8k16.row.col.f32.f16.f16.f32 "
        "{%0,%1,%2,%3}, {%4,%5,%6,%7}, {%8,%9}, {%0,%1,%2,%3};"
        : "+f"(d0), "+f"(d1), "+f"(d2), "+f"(d3)
        : "r"(a0), "r"(a1), "r"(a2), "r"(a3), "r"(b0), "r"(b1));
}

__device__ __forceinline__ void ldsm4(unsigned r[4], uint32_t addr) {
    asm volatile("ldmatrix.sync.aligned.m8n8.x4.shared.b16 {%0,%1,%2,%3}, [%4];"
        : "=r"(r[0]), "=r"(r[1]), "=r"(r[2]), "=r"(r[3]) : "r"(addr));
}

// ============================================================================
// Kernel 0: W (fp32 [k][n]) -> g_WT (fp16 [n][k]).  Tiled smem transpose:
// coalesced reads AND writes.  Grid (12,12), block (32,8).
// ============================================================================
__global__ void wtrans_fast(const float* __restrict__ W) {
    __shared__ float tile[32][33];
    const int kb = blockIdx.x * 32;
    const int nb = blockIdx.y * 32;
    const int tx = threadIdx.x;
    const int ty = threadIdx.y;
    #pragma unroll
    for (int i = 0; i < 4; ++i)
        tile[ty + 8 * i][tx] = W[(size_t)(kb + ty + 8 * i) * DDIM + nb + tx];
    __syncthreads();
    #pragma unroll
    for (int i = 0; i < 4; ++i)
        g_WT[(size_t)(nb + ty + 8 * i) * DDIM + kb + tx] =
            __float2half_rn(tile[tx][ty + 8 * i]);
}

#define NTHR 256
#define BN2  128
#define BK2  64
#define NCHUNK (DDIM / BK2)            // 6
#define ROWB 144
#define B_STG (BN2 * ROWB)             // 18432 B

// ============================================================================
// Kernel 1: PW = P @ W (flat [16384,384] x WT), BM=128 tiles, grid (3,128).
// Phase A: fp32 P rows -> fp16 persistent smem A chunks (+ g_Phalf if jBase==0).
// First two B stages issued BEFORE phase A so their latency hides under it.
// Mainloop: A persistent, B (WT rows) streamed via 3-stage cp.async.
// ============================================================================
#define K1_A_BYTES (NCHUNK * 128 * ROWB)          // 110592
#define SMEM_K1    (K1_A_BYTES + 3 * B_STG)       // 165888

__global__ __launch_bounds__(NTHR, 1)
void gemm_pw_f16(const float* __restrict__ P) {
    extern __shared__ char sm[];
    const uint32_t sm_base = smem_u32(sm);
    const int t    = threadIdx.x;
    const int lane = t & 31;
    const int warp = t >> 5;
    const int wR   = warp & 3;
    const int wC   = warp >> 2;
    const int iBase = blockIdx.y * 128;
    const int jBase = blockIdx.x * BN2;

    auto fillB = [&](int c, int s) {
        const uint32_t b_u32 = sm_base + K1_A_BYTES + (uint32_t)(s * B_STG);
        #pragma unroll
        for (int p = 0; p < 4; ++p) {
            int id  = t + p * NTHR;
            int r   = id >> 3;
            int seg = id & 7;
            cp_async16(b_u32 + (uint32_t)(r * ROWB + seg * 16),
                       &g_WT[(size_t)(jBase + r) * DDIM + c * BK2 + seg * 8]);
        }
    };
    // Issue first two B stages up front; they land while phase A converts.
    fillB(0, 0); CP_COMMIT();
    fillB(1, 1); CP_COMMIT();

    // ---- Phase A: fp32 P rows -> fp16 persistent smem (+ g_Phalf if jBase==0)
    #pragma unroll
    for (int ch = 0; ch < NCHUNK; ++ch) {
        const uint32_t aoffb = (uint32_t)(ch * 128 * ROWB);
        #pragma unroll
        for (int p = 0; p < 8; ++p) {               // 128 rows x 16 f4 = 2048
            int id = t + p * NTHR;
            int r  = id >> 4;
            int f4 = id & 15;
            float4 v = *reinterpret_cast<const float4*>(
                &P[(size_t)(iBase + r) * DDIM + ch * 64 + f4 * 4]);
            __half2 h0 = __floats2half2_rn(v.x, v.y);
            __half2 h1 = __floats2half2_rn(v.z, v.w);
            uint2 o;
            o.x = *reinterpret_cast<unsigned*>(&h0);
            o.y = *reinterpret_cast<unsigned*>(&h1);
            *reinterpret_cast<uint2*>(sm + aoffb + r * ROWB + f4 * 8) = o;
            if (jBase == 0)
                *reinterpret_cast<uint2*>(
                    &g_Phalf[(size_t)(iBase + r) * DDIM + ch * 64 + f4 * 4]) = o;
        }
    }
    __syncthreads();

    const int g  = lane >> 3;
    const int rr = lane & 7;
    const uint32_t aoff = (uint32_t)(rr * ROWB + (g & 1) * (8 * ROWB) + (g >> 1) * 16);
    const uint32_t boff = (uint32_t)(rr * ROWB + (g >> 1) * (8 * ROWB) + (g & 1) * 16);

    float acc[2][8][4];
    #pragma unroll
    for (int mt = 0; mt < 2; ++mt)
        #pragma unroll
        for (int nt = 0; nt < 8; ++nt)
            #pragma unroll
            for (int r = 0; r < 4; ++r) acc[mt][nt][r] = 0.f;

    for (int c = 0; c < NCHUNK; ++c) {
        if (c + 2 < NCHUNK) fillB(c + 2, (c + 2) % 3);
        CP_COMMIT();
        CP_WAIT2();
        __syncthreads();

        const uint32_t As = sm_base + (uint32_t)(c * 128 * ROWB);
        const uint32_t Bs = sm_base + K1_A_BYTES + (uint32_t)((c % 3) * B_STG);
        const uint32_t Abase = As + (uint32_t)(wR * 32 * ROWB) + aoff;
        const uint32_t Bbase = Bs + (uint32_t)(wC * 64 * ROWB) + boff;

        #pragma unroll
        for (int ks = 0; ks < 4; ++ks) {
            const uint32_t cb = ks * 32;
            unsigned a[2][4], bf[8][2];
            #pragma unroll
            for (int mt = 0; mt < 2; ++mt)
                ldsm4(a[mt], Abase + (uint32_t)(mt * 16 * ROWB) + cb);
            #pragma unroll
            for (int np = 0; np < 4; ++np) {
                unsigned bq[4];
                ldsm4(bq, Bbase + (uint32_t)(np * 16 * ROWB) + cb);
                bf[2 * np][0]     = bq[0];
                bf[2 * np][1]     = bq[1];
                bf[2 * np + 1][0] = bq[2];
                bf[2 * np + 1][1] = bq[3];
            }
            #pragma unroll
            for (int mt = 0; mt < 2; ++mt)
                #pragma unroll
                for (int nt = 0; nt < 8; ++nt)
                    mma_f16(acc[mt][nt][0], acc[mt][nt][1], acc[mt][nt][2], acc[mt][nt][3],
                            a[mt][0], a[mt][1], a[mt][2], a[mt][3],
                            bf[nt][0], bf[nt][1]);
        }
        __syncthreads();
    }

    #pragma unroll
    for (int mt = 0; mt < 2; ++mt) {
        int r0 = iBase + wR * 32 + mt * 16 + (lane >> 2);
        #pragma unroll
        for (int nt = 0; nt < 8; ++nt) {
            int cc = jBase + wC * 64 + nt * 8 + ((lane & 3) << 1);
            __half2 h01 = __floats2half2_rn(acc[mt][nt][0], acc[mt][nt][1]);
            __half2 h23 = __floats2half2_rn(acc[mt][nt][2], acc[mt][nt][3]);
            *reinterpret_cast<__half2*>(&g_PW[(size_t)r0 * DDIM + cc])       = h01;
            *reinterpret_cast<__half2*>(&g_PW[(size_t)(r0 + 8) * DDIM + cc]) = h23;
        }
    }
}

// ============================================================================
// Kernel 2 (UNCHANGED — 98.5% of legacy tensor roofline):
// logits[b] = PW[b] @ P[b]^T + bias, BM=256, grid (16,8,8) monolithic.
// ============================================================================
#define K2_A_STG (256 * ROWB)
#define K2_STG   (K2_A_STG + B_STG)
#define SMEM_K2  (3 * K2_STG)                    // 165888

__global__ __launch_bounds__(NTHR, 1)
void gemm_logits_k2(const float* __restrict__ bias_ptr, float* __restrict__ C) {
    extern __shared__ char sm[];
    const uint32_t sm_base = smem_u32(sm);
    const int t    = threadIdx.x;
    const int lane = t & 31;
    const int warp = t >> 5;
    const int wR   = warp & 3;
    const int wC   = warp >> 2;
    const int batch = blockIdx.z;
    const int iBase = blockIdx.y * 256;
    const int jBase = blockIdx.x * BN2;

    const __half* Ag = g_PW    + (size_t)batch * NSEQ * DDIM;
    const __half* Bg = g_Phalf + (size_t)batch * NSEQ * DDIM;
    float* Cb = C + (size_t)batch * NSEQ * NSEQ;

    float acc[4][8][4];
    #pragma unroll
    for (int mt = 0; mt < 4; ++mt)
        #pragma unroll
        for (int nt = 0; nt < 8; ++nt)
            #pragma unroll
            for (int r = 0; r < 4; ++r) acc[mt][nt][r] = 0.f;

    auto fill = [&](int c, int s) {
        const int kc = c * BK2;
        const uint32_t a_u32 = sm_base + (uint32_t)(s * K2_STG);
        const uint32_t b_u32 = a_u32 + K2_A_STG;
        #pragma unroll
        for (int p = 0; p < 8; ++p) {
            int id  = t + p * NTHR;
            int r   = id >> 3;
            int seg = id & 7;
            cp_async16(a_u32 + (uint32_t)(r * ROWB + seg * 16),
                       &Ag[(size_t)(iBase + r) * DDIM + kc + seg * 8]);
        }
        #pragma unroll
        for (int p = 0; p < 4; ++p) {
            int id  = t + p * NTHR;
            int r   = id >> 3;
            int seg = id & 7;
            cp_async16(b_u32 + (uint32_t)(r * ROWB + seg * 16),
                       &Bg[(size_t)(jBase + r) * DDIM + kc + seg * 8]);
        }
    };

    fill(0, 0); CP_COMMIT();
    fill(1, 1); CP_COMMIT();

    const int g  = lane >> 3;
    const int rr = lane & 7;
    const uint32_t aoff = (uint32_t)(rr * ROWB + (g & 1) * (8 * ROWB) + (g >> 1) * 16);
    const uint32_t boff = (uint32_t)(rr * ROWB + (g >> 1) * (8 * ROWB) + (g & 1) * 16);

    for (int c = 0; c < NCHUNK; ++c) {
        if (c + 2 < NCHUNK) fill(c + 2, (c + 2) % 3);
        CP_COMMIT();
        CP_WAIT2();
        __syncthreads();

        const uint32_t As = sm_base + (uint32_t)((c % 3) * K2_STG);
        const uint32_t Bs = As + K2_A_STG;
        const uint32_t Abase = As + (uint32_t)(wR * 64 * ROWB) + aoff;
        const uint32_t Bbase = Bs + (uint32_t)(wC * 64 * ROWB) + boff;

        #pragma unroll
        for (int ks = 0; ks < 4; ++ks) {
            const uint32_t cb = ks * 32;
            unsigned a[4][4], bf[8][2];
            #pragma unroll
            for (int mt = 0; mt < 4; ++mt)
                ldsm4(a[mt], Abase + (uint32_t)(mt * 16 * ROWB) + cb);
            #pragma unroll
            for (int np = 0; np < 4; ++np) {
                unsigned bq[4];
                ldsm4(bq, Bbase + (uint32_t)(np * 16 * ROWB) + cb);
                bf[2 * np][0]     = bq[0];
                bf[2 * np][1]     = bq[1];
                bf[2 * np + 1][0] = bq[2];
                bf[2 * np + 1][1] = bq[3];
            }
            #pragma unroll
            for (int mt = 0; mt < 4; ++mt)
                #pragma unroll
                for (int nt = 0; nt < 8; ++nt)
                    mma_f16(acc[mt][nt][0], acc[mt][nt][1], acc[mt][nt][2], acc[mt][nt][3],
                            a[mt][0], a[mt][1], a[mt][2], a[mt][3],
                            bf[nt][0], bf[nt][1]);
        }
        __syncthreads();
    }

    const float bv = __ldg(bias_ptr);
    #pragma unroll
    for (int mt = 0; mt < 4; ++mt) {
        int r0 = iBase + wR * 64 + mt * 16 + (lane >> 2);
        #pragma unroll
        for (int nt = 0; nt < 8; ++nt) {
            int cc = jBase + wC * 64 + nt * 8 + ((lane & 3) << 1);
            float2 v01 = make_float2(acc[mt][nt][0] + bv, acc[mt][nt][1] + bv);
            float2 v23 = make_float2(acc[mt][nt][2] + bv, acc[mt][nt][3] + bv);
            *reinterpret_cast<float2*>(&Cb[(size_t)r0 * NSEQ + cc])       = v01;
            *reinterpret_cast<float2*>(&Cb[(size_t)(r0 + 8) * NSEQ + cc]) = v23;
        }
    }
}

extern "C" void kernel_launch(void* const* d_in, const int* in_sizes, int n_in,
                              void* d_out, int out_size) {
    const float* P  = (const float*)d_in[0];   // [8, 2048, 384]
    const float* W  = (const float*)d_in[1];   // [384, 384]
    const float* bp = (const float*)d_in[2];   // [1]
    float* out = (float*)d_out;                // [8, 2048, 2048]
    (void)in_sizes; (void)n_in; (void)out_size;

    static bool attr_set = false;
    if (!attr_set) {
        cudaFuncSetAttribute(gemm_pw_f16,
                             cudaFuncAttributeMaxDynamicSharedMemorySize, SMEM_K1);
        cudaFuncSetAttribute(gemm_logits_k2,
                             cudaFuncAttributeMaxDynamicSharedMemorySize, SMEM_K2);
        attr_set = true;
    }

    // W -> W^T fp16 (tiled, coalesced)
    dim3 gwt(DDIM / 32, DDIM / 32, 1);               // (12,12)
    wtrans_fast<<<gwt, dim3(32, 8, 1)>>>(W);

    // Kernel 1: PW = P @ W, fused P->fp16 conversion (writes g_Phalf too)
    dim3 g1(DDIM / BN2, (BATCH * NSEQ) / 128, 1);    // (3, 128) = 384 CTAs
    gemm_pw_f16<<<g1, NTHR, SMEM_K1>>>(P);

    // Kernel 2: per-batch logits = PW @ P^T + b (monolithic 1024 CTAs)
    dim3 g2(NSEQ / BN2, NSEQ / 256, BATCH);          // (16, 8, 8)
    gemm_logits_k2<<<g2, NTHR, SMEM_K2>>>(bp, out);
}